// round 12
// baseline (speedup 1.0000x reference)
#include <cuda_runtime.h>
#include <cuda_fp16.h>
#include <cstdint>

#define NN   32768
#define EE   524288
#define BBG  64
#define NPGC 512
#define CCH  256
#define FINC 128

// ---------------- scratch (static device globals; no allocation) ----------------
__device__ float g_buf0[NN * CCH];   // GEMM output (h_lin)
__device__ float g_h2[NN * CCH];     // layer-2 output (post ELU)
__device__ float g_es[NN * 4];
__device__ float g_ed[NN * 4];
__device__ int   g_off[NN + 1];
__device__ int   g_srcs[EE];
__device__ float g_vvec[CCH];
__device__ float g_l1[NN];
__device__ float g_l2[NN];
// fp16x2 split buffers
__device__ __half g_a0[NN * CCH];
__device__ __half g_a1[NN * CCH];
__device__ __half g_b0[CCH * CCH];
__device__ __half g_b1[CCH * CCH];

__device__ __forceinline__ float lrelu02(float x) { return x >= 0.f ? x : 0.2f * x; }

__device__ __forceinline__ unsigned int fkey_asc(float f) {
    unsigned int u = __float_as_uint(f);
    return (u & 0x80000000u) ? ~u : (u | 0x80000000u);
}

__device__ __forceinline__ uint32_t smem_u32(const void* p) {
    uint32_t a;
    asm("{ .reg .u64 t; cvta.to.shared.u64 t, %1; cvt.u32.u64 %0, t; }" : "=r"(a) : "l"(p));
    return a;
}

#define CP_ASYNC16(sa, gp) \
    asm volatile("cp.async.cg.shared.global [%0], [%1], 16;" :: "r"(sa), "l"(gp))
#define CP_COMMIT() asm volatile("cp.async.commit_group;" ::: "memory")

// ---------------- fused per-graph CSR build ----------------
__global__ void __launch_bounds__(256) k_csr(const int* __restrict__ src,
                                             const int* __restrict__ dst) {
    __shared__ int cnt[512], off[512], cur[512], wpre[8];
    int g = blockIdx.x, tid = threadIdx.x, lane = tid & 31, wid = tid >> 5;
    cnt[tid] = 0; cnt[tid + 256] = 0;
    cur[tid] = 0; cur[tid + 256] = 0;
    __syncthreads();
    int ebase = g * 8192, nbase = g * 512;
    for (int i = tid; i < 8192; i += 256) atomicAdd(&cnt[dst[ebase + i] - nbase], 1);
    __syncthreads();
    int a = cnt[2 * tid], b = cnt[2 * tid + 1];
    int s = a + b;
#pragma unroll
    for (int d = 1; d < 32; d <<= 1) {
        int n = __shfl_up_sync(0xFFFFFFFFu, s, d);
        if (lane >= d) s += n;
    }
    if (lane == 31) wpre[wid] = s;
    __syncthreads();
    if (wid == 0) {
        int w = (lane < 8) ? wpre[lane] : 0;
#pragma unroll
        for (int d = 1; d < 8; d <<= 1) {
            int n = __shfl_up_sync(0xFFFFFFFFu, w, d);
            if (lane >= d) w += n;
        }
        if (lane < 8) wpre[lane] = w;
    }
    __syncthreads();
    int excl = s - a - b + (wid ? wpre[wid - 1] : 0);
    off[2 * tid] = excl;
    off[2 * tid + 1] = excl + a;
    g_off[nbase + 2 * tid] = ebase + excl;
    g_off[nbase + 2 * tid + 1] = ebase + excl + a;
    if (g == 0 && tid == 0) g_off[NN] = EE;
    __syncthreads();
    for (int i = tid; i < 8192; i += 256) {
        int d = dst[ebase + i] - nbase;
        int p = atomicAdd(&cur[d], 1);
        g_srcs[ebase + off[d] + p] = src[ebase + i];
    }
}

// ---------------- fp16x2 splits ----------------
__global__ void k_splitA(const float* __restrict__ in, __half* __restrict__ o0,
                         __half* __restrict__ o1, int n) {
    int i = blockIdx.x * blockDim.x + threadIdx.x;
    if (i >= n) return;
    float v = in[i];
    __half a0 = __float2half(v);
    float r = v - __half2float(a0);
    o0[i] = a0; o1[i] = __float2half(r);
}
__global__ void k_splitW(const float* __restrict__ W, __half* __restrict__ o0,
                         __half* __restrict__ o1, int K) {
    int i = blockIdx.x * blockDim.x + threadIdx.x;
    if (i >= K * 256) return;
    int k = i >> 8, n = i & 255;
    float v = W[i];
    __half a0 = __float2half(v);
    float r = v - __half2float(a0);
    size_t o = (size_t)n * K + k;
    o0[o] = a0; o1[o] = __float2half(r);
}

// ---------------- 3-term fp16x2 mma.sync GEMM, KC=32, 2 CTAs/SM ----------------
__device__ __forceinline__ void mma16816(float* c, const uint32_t* a, const uint32_t* b) {
    asm volatile(
        "mma.sync.aligned.m16n8k16.row.col.f32.f16.f16.f32 "
        "{%0,%1,%2,%3}, {%4,%5,%6,%7}, {%8,%9}, {%0,%1,%2,%3};"
        : "+f"(c[0]), "+f"(c[1]), "+f"(c[2]), "+f"(c[3])
        : "r"(a[0]), "r"(a[1]), "r"(a[2]), "r"(a[3]), "r"(b[0]), "r"(b[1]));
}

#define SPL   10240
#define ABUF  20480
#define BUFSZ 40960
#define SMEM_MMA (2 * BUFSZ)

template <int NCH>  // K = NCH*32
__global__ void __launch_bounds__(256, 2) k_mma3(
    const __half* __restrict__ A0, const __half* __restrict__ A1,
    const __half* __restrict__ B0, const __half* __restrict__ B1,
    float* __restrict__ C, const float* __restrict__ a_src, const float* __restrict__ a_dst) {
    extern __shared__ char sm[];
    const int K = NCH * 32;
    uint32_t smb = smem_u32(sm);
    int tid = threadIdx.x, lane = tid & 31, wid = tid >> 5;
    int warp_m = wid & 3, warp_n = wid >> 2;
    int bm = blockIdx.x * 128;
    int bn = blockIdx.y;

    const __half* Asp[2] = {A0, A1};
    const __half* Bsp[2] = {B0, B1};

    float acc[2][8][4];
#pragma unroll
    for (int i = 0; i < 2; i++)
#pragma unroll
        for (int j = 0; j < 8; j++)
#pragma unroll
            for (int q = 0; q < 4; q++) acc[i][j][q] = 0.f;

#define ISSUE_CHUNK(kc, buf)                                                          \
    do {                                                                              \
        uint32_t bb = smb + (buf)*BUFSZ;                                              \
        _Pragma("unroll")                                                             \
        for (int t = 0; t < 4; t++) {                                                 \
            int id = t * 256 + tid;                                                   \
            int sp = id >> 9, rr = (id & 511) >> 2, sg = id & 3;                      \
            const __half* gp = Asp[sp] + (size_t)(bm + rr) * K + (kc)*32 + sg * 8;    \
            CP_ASYNC16(bb + sp * SPL + rr * 80 + sg * 16, gp);                        \
        }                                                                             \
        _Pragma("unroll")                                                             \
        for (int t = 0; t < 4; t++) {                                                 \
            int id = t * 256 + tid;                                                   \
            int sp = id >> 9, rr = (id & 511) >> 2, sg = id & 3;                      \
            const __half* gp = Bsp[sp] + (size_t)(bn * 128 + rr) * K + (kc)*32 + sg * 8; \
            CP_ASYNC16(bb + ABUF + sp * SPL + rr * 80 + sg * 16, gp);                 \
        }                                                                             \
        CP_COMMIT();                                                                  \
    } while (0)

    ISSUE_CHUNK(0, 0);

#pragma unroll 1
    for (int kc = 0; kc < NCH; kc++) {
        int buf = kc & 1;
        if (kc + 1 < NCH) {
            ISSUE_CHUNK(kc + 1, buf ^ 1);
            asm volatile("cp.async.wait_group 1;" ::: "memory");
        } else {
            asm volatile("cp.async.wait_group 0;" ::: "memory");
        }
        __syncthreads();

        uint32_t bb = smb + buf * BUFSZ;
#pragma unroll
        for (int ks = 0; ks < 2; ks++) {
            uint32_t afr[2][2][4];
#pragma unroll
            for (int sp = 0; sp < 2; sp++)
#pragma unroll
                for (int mt = 0; mt < 2; mt++) {
                    uint32_t addr = bb + sp * SPL +
                        ((warp_m * 32 + mt * 16 + (lane & 15)) * 40 + ks * 16 + ((lane >> 4) << 3)) * 2;
                    asm volatile("ldmatrix.sync.aligned.m8n8.x4.shared.b16 {%0,%1,%2,%3}, [%4];"
                                 : "=r"(afr[sp][mt][0]), "=r"(afr[sp][mt][1]),
                                   "=r"(afr[sp][mt][2]), "=r"(afr[sp][mt][3])
                                 : "r"(addr));
                }
#pragma unroll
            for (int pb = 0; pb < 2; pb++) {
                uint32_t bfr[4][4];
#pragma unroll
                for (int ntp = 0; ntp < 4; ntp++) {
                    uint32_t addr = bb + ABUF + pb * SPL +
                        ((warp_n * 64 + ntp * 16 + ((lane >> 4) << 3) + (lane & 7)) * 40 +
                         ks * 16 + ((lane >> 3) & 1) * 8) * 2;
                    asm volatile("ldmatrix.sync.aligned.m8n8.x4.shared.b16 {%0,%1,%2,%3}, [%4];"
                                 : "=r"(bfr[ntp][0]), "=r"(bfr[ntp][1]),
                                   "=r"(bfr[ntp][2]), "=r"(bfr[ntp][3])
                                 : "r"(addr));
                }
#pragma unroll
                for (int pa = 0; pa < 2; pa++) {
                    if (pa + pb > 1) continue;
#pragma unroll
                    for (int mt = 0; mt < 2; mt++)
#pragma unroll
                        for (int nt = 0; nt < 8; nt++)
                            mma16816(acc[mt][nt], afr[pa][mt], &bfr[nt >> 1][(nt & 1) * 2]);
                }
            }
        }
        __syncthreads();
    }

    // epilogue: C store + fused es/ed
    int head = bn * 2 + warp_n;
    const float* ws = a_src + head * 64;
    const float* wd = a_dst + head * 64;
    float wsv[16], wdv[16];
#pragma unroll
    for (int nt = 0; nt < 8; nt++) {
        int c0i = nt * 8 + (lane & 3) * 2;
        wsv[nt * 2] = ws[c0i]; wsv[nt * 2 + 1] = ws[c0i + 1];
        wdv[nt * 2] = wd[c0i]; wdv[nt * 2 + 1] = wd[c0i + 1];
    }
#pragma unroll
    for (int mt = 0; mt < 2; mt++) {
        int r0 = bm + warp_m * 32 + mt * 16 + (lane >> 2);
        int r1 = r0 + 8;
        float es0 = 0, ed0 = 0, es1 = 0, ed1 = 0;
#pragma unroll
        for (int nt = 0; nt < 8; nt++) {
            int c0i = bn * 128 + warp_n * 64 + nt * 8 + (lane & 3) * 2;
            es0 += acc[mt][nt][0] * wsv[nt * 2] + acc[mt][nt][1] * wsv[nt * 2 + 1];
            ed0 += acc[mt][nt][0] * wdv[nt * 2] + acc[mt][nt][1] * wdv[nt * 2 + 1];
            es1 += acc[mt][nt][2] * wsv[nt * 2] + acc[mt][nt][3] * wsv[nt * 2 + 1];
            ed1 += acc[mt][nt][2] * wdv[nt * 2] + acc[mt][nt][3] * wdv[nt * 2 + 1];
            *(float2*)(C + (size_t)r0 * 256 + c0i) = make_float2(acc[mt][nt][0], acc[mt][nt][1]);
            *(float2*)(C + (size_t)r1 * 256 + c0i) = make_float2(acc[mt][nt][2], acc[mt][nt][3]);
        }
#pragma unroll
        for (int d = 1; d < 4; d <<= 1) {
            es0 += __shfl_xor_sync(0xFFFFFFFFu, es0, d);
            ed0 += __shfl_xor_sync(0xFFFFFFFFu, ed0, d);
            es1 += __shfl_xor_sync(0xFFFFFFFFu, es1, d);
            ed1 += __shfl_xor_sync(0xFFFFFFFFu, ed1, d);
        }
        if ((lane & 3) == 0) {
            g_es[r0 * 4 + head] = es0; g_ed[r0 * 4 + head] = ed0;
            g_es[r1 * 4 + head] = es1; g_ed[r1 * 4 + head] = ed1;
        }
    }
}

// ---------------- smem-staged GAT aggregation ----------------
// Grid: 512 blocks = (graph g = blockIdx.x>>3, channel slice = blockIdx.x&7).
// Stage h[512 nodes x 32 ch] (64KB) + es/ed for this head (4KB) in smem.
// Warp handles 64 nodes; lane owns 1 channel. Per-channel edge order matches CSR
// order (numerics identical to the gather version).
#define AGG_SMEM (65536 + 4096)
template <bool EMIT_SPLIT>
__global__ void __launch_bounds__(256) k_agg_sm(const float* __restrict__ h,
                                                const float* __restrict__ bias,
                                                float* __restrict__ out) {
    extern __shared__ float asm_[];
    float* h_sm = asm_;            // [512][32]
    float* es_sm = asm_ + 16384;   // [512]
    float* ed_sm = asm_ + 16896;   // [512]

    int bid = blockIdx.x;
    int g = bid >> 3, slice = bid & 7;
    int c0 = slice * 32, head = slice >> 1;
    int nbase = g * 512;
    int tid = threadIdx.x, lane = tid & 31, wid = tid >> 5;

    // stage h slice (coalesced float4)
    for (int i = tid; i < 4096; i += 256) {
        int row = i >> 4, seg = i & 15;  // 16 float4 per... wait 32 ch = 8 float4
        // 512 rows * 8 f4 = 4096 tasks
        row = i >> 3; seg = i & 7;
        float4 v = *(const float4*)(h + (size_t)(nbase + row) * 256 + c0 + seg * 4);
        *(float4*)&h_sm[row * 32 + seg * 4] = v;
    }
    // stage es/ed for this head
    for (int i = tid; i < 512; i += 256) {
        es_sm[i] = g_es[(nbase + i) * 4 + head];
        ed_sm[i] = g_ed[(nbase + i) * 4 + head];
    }
    __syncthreads();

    float bias_v = bias[c0 + lane];

    for (int n0 = wid * 64; n0 < wid * 64 + 64; n0++) {
        int n = nbase + n0;
        float edv = ed_sm[n0];
        int s0 = g_off[n], s1 = g_off[n + 1];

        // self-loop
        float w = __expf(lrelu02(es_sm[n0] + edv));
        float den = w;
        float accv = w * h_sm[n0 * 32 + lane];

        for (int base = s0; base < s1; base += 8) {
            int cnt = s1 - base;
            int ss[8];
            float ee[8];
#pragma unroll
            for (int u = 0; u < 8; u++)
                ss[u] = (u < cnt) ? (__ldg(&g_srcs[base + u]) - nbase) : n0;
#pragma unroll
            for (int u = 0; u < 8; u++) ee[u] = es_sm[ss[u]];
#pragma unroll
            for (int u = 0; u < 8; u++) {
                float wu = (u < cnt) ? __expf(lrelu02(ee[u] + edv)) : 0.f;
                den += wu;
                accv += wu * h_sm[ss[u] * 32 + lane];
            }
        }

        float o = accv / (den + 1e-16f) + bias_v;
        o = o > 0.f ? o : expm1f(o);

        if (EMIT_SPLIT) {
            __half h0v = __float2half(o);
            float r = o - __half2float(h0v);
            size_t off = (size_t)n * 256 + c0 + lane;
            g_a0[off] = h0v;
            g_a1[off] = __float2half(r);
        } else {
            out[(size_t)n * 256 + c0 + lane] = o;
        }
    }
}

// ---------------- v = p1_tw @ p2_sw ----------------
__global__ void k_vvec(const float* __restrict__ p1_tw, const float* __restrict__ p2_sw) {
    int k = threadIdx.x;
    float s = 0.f;
    for (int c = 0; c < 256; c++) s += p1_tw[k * 256 + c] * p2_sw[c];
    g_vvec[k] = s;
}

// ---------------- per-node pooling score logits ----------------
__global__ void k_scores(const float* __restrict__ h2, const float* __restrict__ p1_sw) {
    int n = (blockIdx.x * blockDim.x + threadIdx.x) >> 5;
    int lane = threadIdx.x & 31;
    if (n >= NN) return;
    const float4* hp = (const float4*)(h2 + (size_t)n * 256 + lane * 8);
    const float4* w1 = (const float4*)(p1_sw + lane * 8);
    const float4* w2 = (const float4*)(g_vvec + lane * 8);
    float4 h0 = hp[0], h1 = hp[1];
    float4 a0 = w1[0], a1 = w1[1];
    float4 b0 = w2[0], b1 = w2[1];
    float s1 = h0.x * a0.x + h0.y * a0.y + h0.z * a0.z + h0.w * a0.w +
               h1.x * a1.x + h1.y * a1.y + h1.z * a1.z + h1.w * a1.w;
    float s2 = h0.x * b0.x + h0.y * b0.y + h0.z * b0.z + h0.w * b0.w +
               h1.x * b1.x + h1.y * b1.y + h1.z * b1.z + h1.w * b1.w;
#pragma unroll
    for (int d = 16; d > 0; d >>= 1) {
        s1 += __shfl_xor_sync(0xFFFFFFFFu, s1, d);
        s2 += __shfl_xor_sync(0xFFFFFFFFu, s2, d);
    }
    if (lane == 0) { g_l1[n] = s1; g_l2[n] = s2; }
}

// ---------------- per-graph: double top-k select + mean + classifier ----------------
__device__ __forceinline__ void bitonic_sort(unsigned long long* keys, int n, int tid, int nthreads) {
    for (int k = 2; k <= n; k <<= 1) {
        for (int j = k >> 1; j > 0; j >>= 1) {
            for (int t = tid; t < n; t += nthreads) {
                int ixj = t ^ j;
                if (ixj > t) {
                    bool up = ((t & k) == 0);
                    unsigned long long a = keys[t], b = keys[ixj];
                    if (up ? (a > b) : (a < b)) { keys[t] = b; keys[ixj] = a; }
                }
            }
            __syncthreads();
        }
    }
}

__global__ void __launch_bounds__(256) k_pool(
    const float* __restrict__ h2,
    const float* __restrict__ p1_tw, const float* __restrict__ p1_tb,
    const float* __restrict__ p2_tw, const float* __restrict__ p2_tb,
    const float* __restrict__ c1w, const float* __restrict__ c1b,
    const float* __restrict__ c2w, const float* __restrict__ c2b,
    float* __restrict__ out) {
    __shared__ unsigned long long keys[512];
    __shared__ int idx1[256];
    __shared__ int sel[128];
    __shared__ float bufA[256];
    __shared__ float bufB[256];
    __shared__ float zbuf[64];
    __shared__ float lg[2];

    int g = blockIdx.x;
    int tid = threadIdx.x;

    for (int t = tid; t < 512; t += 256) {
        float v = g_l1[g * NPGC + t];
        keys[t] = ((unsigned long long)(~fkey_asc(v)) << 32) | (unsigned int)t;
    }
    __syncthreads();
    bitonic_sort(keys, 512, tid, 256);
    idx1[tid] = (int)(keys[tid] & 0xFFFFFFFFu);
    __syncthreads();
    {
        float v = g_l2[g * NPGC + idx1[tid]];
        keys[tid] = ((unsigned long long)(~fkey_asc(v)) << 32) | (unsigned int)tid;
    }
    __syncthreads();
    bitonic_sort(keys, 256, tid, 256);
    if (tid < 128) sel[tid] = idx1[(int)(keys[tid] & 0xFFFFFFFFu)];
    __syncthreads();
    {
        float acc = 0.f;
        for (int j = 0; j < 128; j++) acc += h2[(size_t)(g * NPGC + sel[j]) * 256 + tid];
        bufA[tid] = acc * (1.f / 128.f);
    }
    __syncthreads();
    {
        float s = p1_tb[tid];
        for (int k = 0; k < 256; k++) s += bufA[k] * p1_tw[k * 256 + tid];
        bufB[tid] = s;
    }
    __syncthreads();
    {
        float s = p2_tb[tid];
        for (int k = 0; k < 256; k++) s += bufB[k] * p2_tw[k * 256 + tid];
        bufA[tid] = s;
    }
    __syncthreads();
    if (tid < 64) {
        float s = c1b[tid];
        for (int k = 0; k < 256; k++) s += bufA[k] * c1w[k * 64 + tid];
        zbuf[tid] = fmaxf(s, 0.f);
    }
    __syncthreads();
    if (tid < 2) {
        float s = c2b[tid];
        for (int k = 0; k < 64; k++) s += zbuf[k] * c2w[k * 2 + tid];
        lg[tid] = s;
    }
    __syncthreads();
    if (tid < 2) {
        float mx = fmaxf(lg[0], lg[1]);
        float lse = mx + logf(expf(lg[0] - mx) + expf(lg[1] - mx));
        out[g * 2 + tid] = lg[tid] - lse;
    }
}

// ---------------- launch ----------------
extern "C" void kernel_launch(void* const* d_in, const int* in_sizes, int n_in,
                              void* d_out, int out_size) {
    const float* x      = (const float*)d_in[0];
    const int*   ei     = (const int*)d_in[1];
    const float* W1     = (const float*)d_in[3];
    const float* a_src1 = (const float*)d_in[4];
    const float* a_dst1 = (const float*)d_in[5];
    const float* b1     = (const float*)d_in[6];
    const float* W2     = (const float*)d_in[7];
    const float* a_src2 = (const float*)d_in[8];
    const float* a_dst2 = (const float*)d_in[9];
    const float* b2     = (const float*)d_in[10];
    const float* p1_sw  = (const float*)d_in[11];
    const float* p1_tw  = (const float*)d_in[13];
    const float* p1_tb  = (const float*)d_in[14];
    const float* p2_sw  = (const float*)d_in[15];
    const float* p2_tw  = (const float*)d_in[17];
    const float* p2_tb  = (const float*)d_in[18];
    const float* c1w    = (const float*)d_in[19];
    const float* c1b    = (const float*)d_in[20];
    const float* c2w    = (const float*)d_in[21];
    const float* c2b    = (const float*)d_in[22];
    float* out = (float*)d_out;

    const int* src = ei;
    const int* dst = ei + EE;

    float* hlin; cudaGetSymbolAddress((void**)&hlin, g_buf0);
    float* h2;   cudaGetSymbolAddress((void**)&h2, g_h2);
    __half *a0, *a1, *b0, *b1s;
    cudaGetSymbolAddress((void**)&a0, g_a0);
    cudaGetSymbolAddress((void**)&a1, g_a1);
    cudaGetSymbolAddress((void**)&b0, g_b0);
    cudaGetSymbolAddress((void**)&b1s, g_b1);

    cudaFuncSetAttribute(k_mma3<4>, cudaFuncAttributeMaxDynamicSharedMemorySize, SMEM_MMA);
    cudaFuncSetAttribute(k_mma3<8>, cudaFuncAttributeMaxDynamicSharedMemorySize, SMEM_MMA);
    cudaFuncSetAttribute(k_agg_sm<true>, cudaFuncAttributeMaxDynamicSharedMemorySize, AGG_SMEM);
    cudaFuncSetAttribute(k_agg_sm<false>, cudaFuncAttributeMaxDynamicSharedMemorySize, AGG_SMEM);

    // fused CSR build (one block per graph)
    k_csr<<<BBG, 256>>>(src, dst);

    // layer 1: split x,W1 -> mma3 GEMM (fused es/ed) -> smem agg (emits fp16x2 splits)
    k_splitA<<<(NN * FINC) / 256, 256>>>(x, a0, a1, NN * FINC);
    k_splitW<<<(FINC * CCH) / 256, 256>>>(W1, b0, b1s, FINC);
    k_mma3<4><<<dim3(NN / 128, 2), 256, SMEM_MMA>>>(a0, a1, b0, b1s, hlin, a_src1, a_dst1);
    k_agg_sm<true><<<512, 256, AGG_SMEM>>>(hlin, b1, nullptr);

    // layer 2
    k_splitW<<<(CCH * CCH) / 256, 256>>>(W2, b0, b1s, CCH);
    k_mma3<8><<<dim3(NN / 128, 2), 256, SMEM_MMA>>>(a0, a1, b0, b1s, hlin, a_src2, a_dst2);
    k_agg_sm<false><<<512, 256, AGG_SMEM>>>(hlin, b2, h2);

    // pooling scores + final head
    k_vvec<<<1, 256>>>(p1_tw, p2_sw);
    k_scores<<<NN / 8, 256>>>(h2, p1_sw);
    k_pool<<<BBG, 256>>>(h2, p1_tw, p1_tb, p2_tw, p2_tb, c1w, c1b, c2w, c2b, out);
}

// round 13
// speedup vs baseline: 1.4344x; 1.4344x over previous
#include <cuda_runtime.h>
#include <cuda_fp16.h>
#include <cstdint>

#define NN   32768
#define EE   524288
#define BBG  64
#define NPGC 512
#define CCH  256
#define FINC 128

// ---------------- scratch (static device globals; no allocation) ----------------
__device__ float g_buf0[NN * CCH];   // GEMM output (h_lin)
__device__ float g_h2[NN * CCH];     // layer-2 output (post ELU)
__device__ float g_es[NN * 4];
__device__ float g_ed[NN * 4];
__device__ int   g_off[NN + 1];
__device__ int   g_srcs[EE];
__device__ float g_vvec[CCH];
__device__ float g_l1[NN];
__device__ float g_l2[NN];
// fp16x2 split buffers
__device__ __half g_a0[NN * CCH];
__device__ __half g_a1[NN * CCH];
__device__ __half g_b0[CCH * CCH];
__device__ __half g_b1[CCH * CCH];

__device__ __forceinline__ float lrelu02(float x) { return x >= 0.f ? x : 0.2f * x; }

__device__ __forceinline__ unsigned int fkey_asc(float f) {
    unsigned int u = __float_as_uint(f);
    return (u & 0x80000000u) ? ~u : (u | 0x80000000u);
}

__device__ __forceinline__ uint32_t smem_u32(const void* p) {
    uint32_t a;
    asm("{ .reg .u64 t; cvta.to.shared.u64 t, %1; cvt.u32.u64 %0, t; }" : "=r"(a) : "l"(p));
    return a;
}

#define CP_ASYNC16(sa, gp) \
    asm volatile("cp.async.cg.shared.global [%0], [%1], 16;" :: "r"(sa), "l"(gp))
#define CP_COMMIT() asm volatile("cp.async.commit_group;" ::: "memory")

// ---------------- fused per-graph CSR build ----------------
__global__ void __launch_bounds__(256) k_csr(const int* __restrict__ src,
                                             const int* __restrict__ dst) {
    __shared__ int cnt[512], off[512], cur[512], wpre[8];
    int g = blockIdx.x, tid = threadIdx.x, lane = tid & 31, wid = tid >> 5;
    cnt[tid] = 0; cnt[tid + 256] = 0;
    cur[tid] = 0; cur[tid + 256] = 0;
    __syncthreads();
    int ebase = g * 8192, nbase = g * 512;
    for (int i = tid; i < 8192; i += 256) atomicAdd(&cnt[dst[ebase + i] - nbase], 1);
    __syncthreads();
    int a = cnt[2 * tid], b = cnt[2 * tid + 1];
    int s = a + b;
#pragma unroll
    for (int d = 1; d < 32; d <<= 1) {
        int n = __shfl_up_sync(0xFFFFFFFFu, s, d);
        if (lane >= d) s += n;
    }
    if (lane == 31) wpre[wid] = s;
    __syncthreads();
    if (wid == 0) {
        int w = (lane < 8) ? wpre[lane] : 0;
#pragma unroll
        for (int d = 1; d < 8; d <<= 1) {
            int n = __shfl_up_sync(0xFFFFFFFFu, w, d);
            if (lane >= d) w += n;
        }
        if (lane < 8) wpre[lane] = w;
    }
    __syncthreads();
    int excl = s - a - b + (wid ? wpre[wid - 1] : 0);
    off[2 * tid] = excl;
    off[2 * tid + 1] = excl + a;
    g_off[nbase + 2 * tid] = ebase + excl;
    g_off[nbase + 2 * tid + 1] = ebase + excl + a;
    if (g == 0 && tid == 0) g_off[NN] = EE;
    __syncthreads();
    for (int i = tid; i < 8192; i += 256) {
        int d = dst[ebase + i] - nbase;
        int p = atomicAdd(&cur[d], 1);
        g_srcs[ebase + off[d] + p] = src[ebase + i];
    }
}

// ---------------- fp16x2 splits ----------------
__global__ void k_splitA(const float* __restrict__ in, __half* __restrict__ o0,
                         __half* __restrict__ o1, int n) {
    int i = blockIdx.x * blockDim.x + threadIdx.x;
    if (i >= n) return;
    float v = in[i];
    __half a0 = __float2half(v);
    float r = v - __half2float(a0);
    o0[i] = a0; o1[i] = __float2half(r);
}
__global__ void k_splitW(const float* __restrict__ W, __half* __restrict__ o0,
                         __half* __restrict__ o1, int K) {
    int i = blockIdx.x * blockDim.x + threadIdx.x;
    if (i >= K * 256) return;
    int k = i >> 8, n = i & 255;
    float v = W[i];
    __half a0 = __float2half(v);
    float r = v - __half2float(a0);
    size_t o = (size_t)n * K + k;
    o0[o] = a0; o1[o] = __float2half(r);
}

// ---------------- 3-term fp16x2 mma.sync GEMM, KC=32, 2 CTAs/SM ----------------
__device__ __forceinline__ void mma16816(float* c, const uint32_t* a, const uint32_t* b) {
    asm volatile(
        "mma.sync.aligned.m16n8k16.row.col.f32.f16.f16.f32 "
        "{%0,%1,%2,%3}, {%4,%5,%6,%7}, {%8,%9}, {%0,%1,%2,%3};"
        : "+f"(c[0]), "+f"(c[1]), "+f"(c[2]), "+f"(c[3])
        : "r"(a[0]), "r"(a[1]), "r"(a[2]), "r"(a[3]), "r"(b[0]), "r"(b[1]));
}

#define SPL   10240
#define ABUF  20480
#define BUFSZ 40960
#define SMEM_MMA (2 * BUFSZ)

template <int NCH>  // K = NCH*32
__global__ void __launch_bounds__(256, 2) k_mma3(
    const __half* __restrict__ A0, const __half* __restrict__ A1,
    const __half* __restrict__ B0, const __half* __restrict__ B1,
    float* __restrict__ C, const float* __restrict__ a_src, const float* __restrict__ a_dst) {
    extern __shared__ char sm[];
    const int K = NCH * 32;
    uint32_t smb = smem_u32(sm);
    int tid = threadIdx.x, lane = tid & 31, wid = tid >> 5;
    int warp_m = wid & 3, warp_n = wid >> 2;
    int bm = blockIdx.x * 128;
    int bn = blockIdx.y;

    const __half* Asp[2] = {A0, A1};
    const __half* Bsp[2] = {B0, B1};

    float acc[2][8][4];
#pragma unroll
    for (int i = 0; i < 2; i++)
#pragma unroll
        for (int j = 0; j < 8; j++)
#pragma unroll
            for (int q = 0; q < 4; q++) acc[i][j][q] = 0.f;

#define ISSUE_CHUNK(kc, buf)                                                          \
    do {                                                                              \
        uint32_t bb = smb + (buf)*BUFSZ;                                              \
        _Pragma("unroll")                                                             \
        for (int t = 0; t < 4; t++) {                                                 \
            int id = t * 256 + tid;                                                   \
            int sp = id >> 9, rr = (id & 511) >> 2, sg = id & 3;                      \
            const __half* gp = Asp[sp] + (size_t)(bm + rr) * K + (kc)*32 + sg * 8;    \
            CP_ASYNC16(bb + sp * SPL + rr * 80 + sg * 16, gp);                        \
        }                                                                             \
        _Pragma("unroll")                                                             \
        for (int t = 0; t < 4; t++) {                                                 \
            int id = t * 256 + tid;                                                   \
            int sp = id >> 9, rr = (id & 511) >> 2, sg = id & 3;                      \
            const __half* gp = Bsp[sp] + (size_t)(bn * 128 + rr) * K + (kc)*32 + sg * 8; \
            CP_ASYNC16(bb + ABUF + sp * SPL + rr * 80 + sg * 16, gp);                 \
        }                                                                             \
        CP_COMMIT();                                                                  \
    } while (0)

    ISSUE_CHUNK(0, 0);

#pragma unroll 1
    for (int kc = 0; kc < NCH; kc++) {
        int buf = kc & 1;
        if (kc + 1 < NCH) {
            ISSUE_CHUNK(kc + 1, buf ^ 1);
            asm volatile("cp.async.wait_group 1;" ::: "memory");
        } else {
            asm volatile("cp.async.wait_group 0;" ::: "memory");
        }
        __syncthreads();

        uint32_t bb = smb + buf * BUFSZ;
#pragma unroll
        for (int ks = 0; ks < 2; ks++) {
            uint32_t afr[2][2][4];
#pragma unroll
            for (int sp = 0; sp < 2; sp++)
#pragma unroll
                for (int mt = 0; mt < 2; mt++) {
                    uint32_t addr = bb + sp * SPL +
                        ((warp_m * 32 + mt * 16 + (lane & 15)) * 40 + ks * 16 + ((lane >> 4) << 3)) * 2;
                    asm volatile("ldmatrix.sync.aligned.m8n8.x4.shared.b16 {%0,%1,%2,%3}, [%4];"
                                 : "=r"(afr[sp][mt][0]), "=r"(afr[sp][mt][1]),
                                   "=r"(afr[sp][mt][2]), "=r"(afr[sp][mt][3])
                                 : "r"(addr));
                }
#pragma unroll
            for (int pb = 0; pb < 2; pb++) {
                uint32_t bfr[4][4];
#pragma unroll
                for (int ntp = 0; ntp < 4; ntp++) {
                    uint32_t addr = bb + ABUF + pb * SPL +
                        ((warp_n * 64 + ntp * 16 + ((lane >> 4) << 3) + (lane & 7)) * 40 +
                         ks * 16 + ((lane >> 3) & 1) * 8) * 2;
                    asm volatile("ldmatrix.sync.aligned.m8n8.x4.shared.b16 {%0,%1,%2,%3}, [%4];"
                                 : "=r"(bfr[ntp][0]), "=r"(bfr[ntp][1]),
                                   "=r"(bfr[ntp][2]), "=r"(bfr[ntp][3])
                                 : "r"(addr));
                }
#pragma unroll
                for (int pa = 0; pa < 2; pa++) {
                    if (pa + pb > 1) continue;
#pragma unroll
                    for (int mt = 0; mt < 2; mt++)
#pragma unroll
                        for (int nt = 0; nt < 8; nt++)
                            mma16816(acc[mt][nt], afr[pa][mt], &bfr[nt >> 1][(nt & 1) * 2]);
                }
            }
        }
        __syncthreads();
    }

    // epilogue: C store + fused es/ed
    int head = bn * 2 + warp_n;
    const float* ws = a_src + head * 64;
    const float* wd = a_dst + head * 64;
    float wsv[16], wdv[16];
#pragma unroll
    for (int nt = 0; nt < 8; nt++) {
        int c0i = nt * 8 + (lane & 3) * 2;
        wsv[nt * 2] = ws[c0i]; wsv[nt * 2 + 1] = ws[c0i + 1];
        wdv[nt * 2] = wd[c0i]; wdv[nt * 2 + 1] = wd[c0i + 1];
    }
#pragma unroll
    for (int mt = 0; mt < 2; mt++) {
        int r0 = bm + warp_m * 32 + mt * 16 + (lane >> 2);
        int r1 = r0 + 8;
        float es0 = 0, ed0 = 0, es1 = 0, ed1 = 0;
#pragma unroll
        for (int nt = 0; nt < 8; nt++) {
            int c0i = bn * 128 + warp_n * 64 + nt * 8 + (lane & 3) * 2;
            es0 += acc[mt][nt][0] * wsv[nt * 2] + acc[mt][nt][1] * wsv[nt * 2 + 1];
            ed0 += acc[mt][nt][0] * wdv[nt * 2] + acc[mt][nt][1] * wdv[nt * 2 + 1];
            es1 += acc[mt][nt][2] * wsv[nt * 2] + acc[mt][nt][3] * wsv[nt * 2 + 1];
            ed1 += acc[mt][nt][2] * wdv[nt * 2] + acc[mt][nt][3] * wdv[nt * 2 + 1];
            *(float2*)(C + (size_t)r0 * 256 + c0i) = make_float2(acc[mt][nt][0], acc[mt][nt][1]);
            *(float2*)(C + (size_t)r1 * 256 + c0i) = make_float2(acc[mt][nt][2], acc[mt][nt][3]);
        }
#pragma unroll
        for (int d = 1; d < 4; d <<= 1) {
            es0 += __shfl_xor_sync(0xFFFFFFFFu, es0, d);
            ed0 += __shfl_xor_sync(0xFFFFFFFFu, ed0, d);
            es1 += __shfl_xor_sync(0xFFFFFFFFu, es1, d);
            ed1 += __shfl_xor_sync(0xFFFFFFFFu, ed1, d);
        }
        if ((lane & 3) == 0) {
            g_es[r0 * 4 + head] = es0; g_ed[r0 * 4 + head] = ed0;
            g_es[r1 * 4 + head] = es1; g_ed[r1 * 4 + head] = ed1;
        }
    }
}

// ---------------- smem-staged GAT aggregation (v2: srcs/off staged, 16 warps) ----------------
// Grid: 512 blocks = (graph g = blockIdx.x>>3, channel slice = blockIdx.x&7).
// smem: h slice [512x32] fp32 (64KB) + es/ed head (4KB) + srcs (32KB) + off (2KB).
// NO global loads in the edge loop. Warp handles 32 nodes; lane owns 1 channel.
// Accumulation order per channel identical to the R11 gather version.
#define AGG_F_H    0        // h_sm: 16384 floats
#define AGG_F_ES   16384    // es_sm: 512
#define AGG_F_ED   16896    // ed_sm: 512
#define AGG_F_OFF  17408    // off_sm: 513 ints
#define AGG_F_SRC  17924    // srcs_sm: 8192 ints (16B aligned)
#define AGG_SMEM   ((17924 + 8192) * 4)

template <bool EMIT_SPLIT>
__global__ void __launch_bounds__(512, 2) k_agg_sm(const float* __restrict__ h,
                                                   const float* __restrict__ bias,
                                                   float* __restrict__ out) {
    extern __shared__ float asm_[];
    float* h_sm  = asm_ + AGG_F_H;
    float* es_sm = asm_ + AGG_F_ES;
    float* ed_sm = asm_ + AGG_F_ED;
    int*   off_sm  = (int*)(asm_ + AGG_F_OFF);
    int*   srcs_sm = (int*)(asm_ + AGG_F_SRC);

    int bid = blockIdx.x;
    int g = bid >> 3, slice = bid & 7;
    int c0 = slice * 32, head = slice >> 1;
    int nbase = g * 512, ebase = g * 8192;
    int tid = threadIdx.x, lane = tid & 31, wid = tid >> 5;

    // stage h slice: 512 rows x 8 float4 = 4096 tasks
    for (int i = tid; i < 4096; i += 512) {
        int row = i >> 3, seg = i & 7;
        float4 v = *(const float4*)(h + (size_t)(nbase + row) * 256 + c0 + seg * 4);
        *(float4*)&h_sm[row * 32 + seg * 4] = v;
    }
    // stage es/ed for this head
    {
        int i = tid;
        if (i < 512) {
            es_sm[i] = g_es[(nbase + i) * 4 + head];
            ed_sm[i] = g_ed[(nbase + i) * 4 + head];
        }
    }
    // stage offsets (graph-relative)
    for (int i = tid; i < 513; i += 512) off_sm[i] = g_off[nbase + i] - ebase;
    // stage srcs (graph-relative), int4
    {
        const int4* gs = (const int4*)(g_srcs + ebase);
        for (int i = tid; i < 2048; i += 512) {
            int4 v = gs[i];
            v.x -= nbase; v.y -= nbase; v.z -= nbase; v.w -= nbase;
            *(int4*)&srcs_sm[i * 4] = v;
        }
    }
    __syncthreads();

    float bias_v = bias[c0 + lane];

    for (int n0 = wid * 32; n0 < wid * 32 + 32; n0++) {
        float edv = ed_sm[n0];
        int s0 = off_sm[n0], s1 = off_sm[n0 + 1];

        // self-loop
        float w = __expf(lrelu02(es_sm[n0] + edv));
        float den = w;
        float accv = w * h_sm[n0 * 32 + lane];

        for (int base = s0; base < s1; base += 8) {
            int cnt = s1 - base;
            int ss[8];
            float ee[8];
#pragma unroll
            for (int u = 0; u < 8; u++) ss[u] = (u < cnt) ? srcs_sm[base + u] : n0;
#pragma unroll
            for (int u = 0; u < 8; u++) ee[u] = es_sm[ss[u]];
#pragma unroll
            for (int u = 0; u < 8; u++) {
                float wu = (u < cnt) ? __expf(lrelu02(ee[u] + edv)) : 0.f;
                den += wu;
                accv += wu * h_sm[ss[u] * 32 + lane];
            }
        }

        float o = accv / (den + 1e-16f) + bias_v;
        o = o > 0.f ? o : expm1f(o);

        int n = nbase + n0;
        if (EMIT_SPLIT) {
            __half h0v = __float2half(o);
            float r = o - __half2float(h0v);
            size_t off = (size_t)n * 256 + c0 + lane;
            g_a0[off] = h0v;
            g_a1[off] = __float2half(r);
        } else {
            out[(size_t)n * 256 + c0 + lane] = o;
        }
    }
}

// ---------------- v = p1_tw @ p2_sw ----------------
__global__ void k_vvec(const float* __restrict__ p1_tw, const float* __restrict__ p2_sw) {
    int k = threadIdx.x;
    float s = 0.f;
    for (int c = 0; c < 256; c++) s += p1_tw[k * 256 + c] * p2_sw[c];
    g_vvec[k] = s;
}

// ---------------- per-node pooling score logits ----------------
__global__ void k_scores(const float* __restrict__ h2, const float* __restrict__ p1_sw) {
    int n = (blockIdx.x * blockDim.x + threadIdx.x) >> 5;
    int lane = threadIdx.x & 31;
    if (n >= NN) return;
    const float4* hp = (const float4*)(h2 + (size_t)n * 256 + lane * 8);
    const float4* w1 = (const float4*)(p1_sw + lane * 8);
    const float4* w2 = (const float4*)(g_vvec + lane * 8);
    float4 h0 = hp[0], h1 = hp[1];
    float4 a0 = w1[0], a1 = w1[1];
    float4 b0 = w2[0], b1 = w2[1];
    float s1 = h0.x * a0.x + h0.y * a0.y + h0.z * a0.z + h0.w * a0.w +
               h1.x * a1.x + h1.y * a1.y + h1.z * a1.z + h1.w * a1.w;
    float s2 = h0.x * b0.x + h0.y * b0.y + h0.z * b0.z + h0.w * b0.w +
               h1.x * b1.x + h1.y * b1.y + h1.z * b1.z + h1.w * b1.w;
#pragma unroll
    for (int d = 16; d > 0; d >>= 1) {
        s1 += __shfl_xor_sync(0xFFFFFFFFu, s1, d);
        s2 += __shfl_xor_sync(0xFFFFFFFFu, s2, d);
    }
    if (lane == 0) { g_l1[n] = s1; g_l2[n] = s2; }
}

// ---------------- per-graph: double top-k select + mean + classifier ----------------
__device__ __forceinline__ void bitonic_sort(unsigned long long* keys, int n, int tid, int nthreads) {
    for (int k = 2; k <= n; k <<= 1) {
        for (int j = k >> 1; j > 0; j >>= 1) {
            for (int t = tid; t < n; t += nthreads) {
                int ixj = t ^ j;
                if (ixj > t) {
                    bool up = ((t & k) == 0);
                    unsigned long long a = keys[t], b = keys[ixj];
                    if (up ? (a > b) : (a < b)) { keys[t] = b; keys[ixj] = a; }
                }
            }
            __syncthreads();
        }
    }
}

__global__ void __launch_bounds__(256) k_pool(
    const float* __restrict__ h2,
    const float* __restrict__ p1_tw, const float* __restrict__ p1_tb,
    const float* __restrict__ p2_tw, const float* __restrict__ p2_tb,
    const float* __restrict__ c1w, const float* __restrict__ c1b,
    const float* __restrict__ c2w, const float* __restrict__ c2b,
    float* __restrict__ out) {
    __shared__ unsigned long long keys[512];
    __shared__ int idx1[256];
    __shared__ int sel[128];
    __shared__ float bufA[256];
    __shared__ float bufB[256];
    __shared__ float zbuf[64];
    __shared__ float lg[2];

    int g = blockIdx.x;
    int tid = threadIdx.x;

    for (int t = tid; t < 512; t += 256) {
        float v = g_l1[g * NPGC + t];
        keys[t] = ((unsigned long long)(~fkey_asc(v)) << 32) | (unsigned int)t;
    }
    __syncthreads();
    bitonic_sort(keys, 512, tid, 256);
    idx1[tid] = (int)(keys[tid] & 0xFFFFFFFFu);
    __syncthreads();
    {
        float v = g_l2[g * NPGC + idx1[tid]];
        keys[tid] = ((unsigned long long)(~fkey_asc(v)) << 32) | (unsigned int)tid;
    }
    __syncthreads();
    bitonic_sort(keys, 256, tid, 256);
    if (tid < 128) sel[tid] = idx1[(int)(keys[tid] & 0xFFFFFFFFu)];
    __syncthreads();
    {
        float acc = 0.f;
        for (int j = 0; j < 128; j++) acc += h2[(size_t)(g * NPGC + sel[j]) * 256 + tid];
        bufA[tid] = acc * (1.f / 128.f);
    }
    __syncthreads();
    {
        float s = p1_tb[tid];
        for (int k = 0; k < 256; k++) s += bufA[k] * p1_tw[k * 256 + tid];
        bufB[tid] = s;
    }
    __syncthreads();
    {
        float s = p2_tb[tid];
        for (int k = 0; k < 256; k++) s += bufB[k] * p2_tw[k * 256 + tid];
        bufA[tid] = s;
    }
    __syncthreads();
    if (tid < 64) {
        float s = c1b[tid];
        for (int k = 0; k < 256; k++) s += bufA[k] * c1w[k * 64 + tid];
        zbuf[tid] = fmaxf(s, 0.f);
    }
    __syncthreads();
    if (tid < 2) {
        float s = c2b[tid];
        for (int k = 0; k < 64; k++) s += zbuf[k] * c2w[k * 2 + tid];
        lg[tid] = s;
    }
    __syncthreads();
    if (tid < 2) {
        float mx = fmaxf(lg[0], lg[1]);
        float lse = mx + logf(expf(lg[0] - mx) + expf(lg[1] - mx));
        out[g * 2 + tid] = lg[tid] - lse;
    }
}

// ---------------- launch ----------------
extern "C" void kernel_launch(void* const* d_in, const int* in_sizes, int n_in,
                              void* d_out, int out_size) {
    const float* x      = (const float*)d_in[0];
    const int*   ei     = (const int*)d_in[1];
    const float* W1     = (const float*)d_in[3];
    const float* a_src1 = (const float*)d_in[4];
    const float* a_dst1 = (const float*)d_in[5];
    const float* b1     = (const float*)d_in[6];
    const float* W2     = (const float*)d_in[7];
    const float* a_src2 = (const float*)d_in[8];
    const float* a_dst2 = (const float*)d_in[9];
    const float* b2     = (const float*)d_in[10];
    const float* p1_sw  = (const float*)d_in[11];
    const float* p1_tw  = (const float*)d_in[13];
    const float* p1_tb  = (const float*)d_in[14];
    const float* p2_sw  = (const float*)d_in[15];
    const float* p2_tw  = (const float*)d_in[17];
    const float* p2_tb  = (const float*)d_in[18];
    const float* c1w    = (const float*)d_in[19];
    const float* c1b    = (const float*)d_in[20];
    const float* c2w    = (const float*)d_in[21];
    const float* c2b    = (const float*)d_in[22];
    float* out = (float*)d_out;

    const int* src = ei;
    const int* dst = ei + EE;

    float* hlin; cudaGetSymbolAddress((void**)&hlin, g_buf0);
    float* h2;   cudaGetSymbolAddress((void**)&h2, g_h2);
    __half *a0, *a1, *b0, *b1s;
    cudaGetSymbolAddress((void**)&a0, g_a0);
    cudaGetSymbolAddress((void**)&a1, g_a1);
    cudaGetSymbolAddress((void**)&b0, g_b0);
    cudaGetSymbolAddress((void**)&b1s, g_b1);

    cudaFuncSetAttribute(k_mma3<4>, cudaFuncAttributeMaxDynamicSharedMemorySize, SMEM_MMA);
    cudaFuncSetAttribute(k_mma3<8>, cudaFuncAttributeMaxDynamicSharedMemorySize, SMEM_MMA);
    cudaFuncSetAttribute(k_agg_sm<true>, cudaFuncAttributeMaxDynamicSharedMemorySize, AGG_SMEM);
    cudaFuncSetAttribute(k_agg_sm<false>, cudaFuncAttributeMaxDynamicSharedMemorySize, AGG_SMEM);

    // fused CSR build (one block per graph)
    k_csr<<<BBG, 256>>>(src, dst);

    // layer 1: split x,W1 -> mma3 GEMM (fused es/ed) -> smem agg (emits fp16x2 splits)
    k_splitA<<<(NN * FINC) / 256, 256>>>(x, a0, a1, NN * FINC);
    k_splitW<<<(FINC * CCH) / 256, 256>>>(W1, b0, b1s, FINC);
    k_mma3<4><<<dim3(NN / 128, 2), 256, SMEM_MMA>>>(a0, a1, b0, b1s, hlin, a_src1, a_dst1);
    k_agg_sm<true><<<512, 512, AGG_SMEM>>>(hlin, b1, nullptr);

    // layer 2
    k_splitW<<<(CCH * CCH) / 256, 256>>>(W2, b0, b1s, CCH);
    k_mma3<8><<<dim3(NN / 128, 2), 256, SMEM_MMA>>>(a0, a1, b0, b1s, hlin, a_src2, a_dst2);
    k_agg_sm<false><<<512, 512, AGG_SMEM>>>(hlin, b2, h2);

    // pooling scores + final head
    k_vvec<<<1, 256>>>(p1_tw, p2_sw);
    k_scores<<<NN / 8, 256>>>(h2, p1_sw);
    k_pool<<<BBG, 256>>>(h2, p1_tw, p1_tb, p2_tw, p2_tb, c1w, c1b, c2w, c2b, out);
}

// round 14
// speedup vs baseline: 2.1563x; 1.5033x over previous
#include <cuda_runtime.h>
#include <cuda_fp16.h>
#include <cstdint>

#define NN   32768
#define EE   524288
#define BBG  64
#define NPGC 512
#define CCH  256
#define FINC 128

// ---------------- scratch (static device globals; no allocation) ----------------
__device__ float g_buf0[NN * CCH];   // GEMM output (h_lin)
__device__ float g_h2[NN * CCH];     // layer-2 output (post ELU)
__device__ float g_es[NN * 4];
__device__ float g_ed[NN * 4];
__device__ int   g_off[NN + 1];
__device__ int   g_srcs[EE];
__device__ float g_vvec[CCH];
__device__ float g_l1[NN];
__device__ float g_l2[NN];
// fp16x2 split buffers
__device__ __half g_a0[NN * CCH];
__device__ __half g_a1[NN * CCH];
__device__ __half g_b0[CCH * CCH];
__device__ __half g_b1[CCH * CCH];

__device__ __forceinline__ float lrelu02(float x) { return x >= 0.f ? x : 0.2f * x; }

__device__ __forceinline__ unsigned int fkey_asc(float f) {
    unsigned int u = __float_as_uint(f);
    return (u & 0x80000000u) ? ~u : (u | 0x80000000u);
}

__device__ __forceinline__ uint32_t smem_u32(const void* p) {
    uint32_t a;
    asm("{ .reg .u64 t; cvta.to.shared.u64 t, %1; cvt.u32.u64 %0, t; }" : "=r"(a) : "l"(p));
    return a;
}

#define CP_ASYNC16(sa, gp) \
    asm volatile("cp.async.cg.shared.global [%0], [%1], 16;" :: "r"(sa), "l"(gp))
#define CP_COMMIT() asm volatile("cp.async.commit_group;" ::: "memory")

// ---------------- fused per-graph CSR build ----------------
__global__ void __launch_bounds__(256) k_csr(const int* __restrict__ src,
                                             const int* __restrict__ dst) {
    __shared__ int cnt[512], off[512], cur[512], wpre[8];
    int g = blockIdx.x, tid = threadIdx.x, lane = tid & 31, wid = tid >> 5;
    cnt[tid] = 0; cnt[tid + 256] = 0;
    cur[tid] = 0; cur[tid + 256] = 0;
    __syncthreads();
    int ebase = g * 8192, nbase = g * 512;
    for (int i = tid; i < 8192; i += 256) atomicAdd(&cnt[dst[ebase + i] - nbase], 1);
    __syncthreads();
    int a = cnt[2 * tid], b = cnt[2 * tid + 1];
    int s = a + b;
#pragma unroll
    for (int d = 1; d < 32; d <<= 1) {
        int n = __shfl_up_sync(0xFFFFFFFFu, s, d);
        if (lane >= d) s += n;
    }
    if (lane == 31) wpre[wid] = s;
    __syncthreads();
    if (wid == 0) {
        int w = (lane < 8) ? wpre[lane] : 0;
#pragma unroll
        for (int d = 1; d < 8; d <<= 1) {
            int n = __shfl_up_sync(0xFFFFFFFFu, w, d);
            if (lane >= d) w += n;
        }
        if (lane < 8) wpre[lane] = w;
    }
    __syncthreads();
    int excl = s - a - b + (wid ? wpre[wid - 1] : 0);
    off[2 * tid] = excl;
    off[2 * tid + 1] = excl + a;
    g_off[nbase + 2 * tid] = ebase + excl;
    g_off[nbase + 2 * tid + 1] = ebase + excl + a;
    if (g == 0 && tid == 0) g_off[NN] = EE;
    __syncthreads();
    for (int i = tid; i < 8192; i += 256) {
        int d = dst[ebase + i] - nbase;
        int p = atomicAdd(&cur[d], 1);
        g_srcs[ebase + off[d] + p] = src[ebase + i];
    }
}

// ---------------- fp16x2 splits ----------------
__global__ void k_splitA(const float* __restrict__ in, __half* __restrict__ o0,
                         __half* __restrict__ o1, int n) {
    int i = blockIdx.x * blockDim.x + threadIdx.x;
    if (i >= n) return;
    float v = in[i];
    __half a0 = __float2half(v);
    float r = v - __half2float(a0);
    o0[i] = a0; o1[i] = __float2half(r);
}
__global__ void k_splitW(const float* __restrict__ W, __half* __restrict__ o0,
                         __half* __restrict__ o1, int K) {
    int i = blockIdx.x * blockDim.x + threadIdx.x;
    if (i >= K * 256) return;
    int k = i >> 8, n = i & 255;
    float v = W[i];
    __half a0 = __float2half(v);
    float r = v - __half2float(a0);
    size_t o = (size_t)n * K + k;
    o0[o] = a0; o1[o] = __float2half(r);
}

// ---------------- 3-term fp16x2 mma.sync GEMM, KC=32, 2 CTAs/SM ----------------
__device__ __forceinline__ void mma16816(float* c, const uint32_t* a, const uint32_t* b) {
    asm volatile(
        "mma.sync.aligned.m16n8k16.row.col.f32.f16.f16.f32 "
        "{%0,%1,%2,%3}, {%4,%5,%6,%7}, {%8,%9}, {%0,%1,%2,%3};"
        : "+f"(c[0]), "+f"(c[1]), "+f"(c[2]), "+f"(c[3])
        : "r"(a[0]), "r"(a[1]), "r"(a[2]), "r"(a[3]), "r"(b[0]), "r"(b[1]));
}

#define SPL   10240
#define ABUF  20480
#define BUFSZ 40960
#define SMEM_MMA (2 * BUFSZ)

template <int NCH>  // K = NCH*32
__global__ void __launch_bounds__(256, 2) k_mma3(
    const __half* __restrict__ A0, const __half* __restrict__ A1,
    const __half* __restrict__ B0, const __half* __restrict__ B1,
    float* __restrict__ C, const float* __restrict__ a_src, const float* __restrict__ a_dst) {
    extern __shared__ char sm[];
    const int K = NCH * 32;
    uint32_t smb = smem_u32(sm);
    int tid = threadIdx.x, lane = tid & 31, wid = tid >> 5;
    int warp_m = wid & 3, warp_n = wid >> 2;
    int bm = blockIdx.x * 128;
    int bn = blockIdx.y;

    const __half* Asp[2] = {A0, A1};
    const __half* Bsp[2] = {B0, B1};

    float acc[2][8][4];
#pragma unroll
    for (int i = 0; i < 2; i++)
#pragma unroll
        for (int j = 0; j < 8; j++)
#pragma unroll
            for (int q = 0; q < 4; q++) acc[i][j][q] = 0.f;

#define ISSUE_CHUNK(kc, buf)                                                          \
    do {                                                                              \
        uint32_t bb = smb + (buf)*BUFSZ;                                              \
        _Pragma("unroll")                                                             \
        for (int t = 0; t < 4; t++) {                                                 \
            int id = t * 256 + tid;                                                   \
            int sp = id >> 9, rr = (id & 511) >> 2, sg = id & 3;                      \
            const __half* gp = Asp[sp] + (size_t)(bm + rr) * K + (kc)*32 + sg * 8;    \
            CP_ASYNC16(bb + sp * SPL + rr * 80 + sg * 16, gp);                        \
        }                                                                             \
        _Pragma("unroll")                                                             \
        for (int t = 0; t < 4; t++) {                                                 \
            int id = t * 256 + tid;                                                   \
            int sp = id >> 9, rr = (id & 511) >> 2, sg = id & 3;                      \
            const __half* gp = Bsp[sp] + (size_t)(bn * 128 + rr) * K + (kc)*32 + sg * 8; \
            CP_ASYNC16(bb + ABUF + sp * SPL + rr * 80 + sg * 16, gp);                 \
        }                                                                             \
        CP_COMMIT();                                                                  \
    } while (0)

    ISSUE_CHUNK(0, 0);

#pragma unroll 1
    for (int kc = 0; kc < NCH; kc++) {
        int buf = kc & 1;
        if (kc + 1 < NCH) {
            ISSUE_CHUNK(kc + 1, buf ^ 1);
            asm volatile("cp.async.wait_group 1;" ::: "memory");
        } else {
            asm volatile("cp.async.wait_group 0;" ::: "memory");
        }
        __syncthreads();

        uint32_t bb = smb + buf * BUFSZ;
#pragma unroll
        for (int ks = 0; ks < 2; ks++) {
            uint32_t afr[2][2][4];
#pragma unroll
            for (int sp = 0; sp < 2; sp++)
#pragma unroll
                for (int mt = 0; mt < 2; mt++) {
                    uint32_t addr = bb + sp * SPL +
                        ((warp_m * 32 + mt * 16 + (lane & 15)) * 40 + ks * 16 + ((lane >> 4) << 3)) * 2;
                    asm volatile("ldmatrix.sync.aligned.m8n8.x4.shared.b16 {%0,%1,%2,%3}, [%4];"
                                 : "=r"(afr[sp][mt][0]), "=r"(afr[sp][mt][1]),
                                   "=r"(afr[sp][mt][2]), "=r"(afr[sp][mt][3])
                                 : "r"(addr));
                }
#pragma unroll
            for (int pb = 0; pb < 2; pb++) {
                uint32_t bfr[4][4];
#pragma unroll
                for (int ntp = 0; ntp < 4; ntp++) {
                    uint32_t addr = bb + ABUF + pb * SPL +
                        ((warp_n * 64 + ntp * 16 + ((lane >> 4) << 3) + (lane & 7)) * 40 +
                         ks * 16 + ((lane >> 3) & 1) * 8) * 2;
                    asm volatile("ldmatrix.sync.aligned.m8n8.x4.shared.b16 {%0,%1,%2,%3}, [%4];"
                                 : "=r"(bfr[ntp][0]), "=r"(bfr[ntp][1]),
                                   "=r"(bfr[ntp][2]), "=r"(bfr[ntp][3])
                                 : "r"(addr));
                }
#pragma unroll
                for (int pa = 0; pa < 2; pa++) {
                    if (pa + pb > 1) continue;
#pragma unroll
                    for (int mt = 0; mt < 2; mt++)
#pragma unroll
                        for (int nt = 0; nt < 8; nt++)
                            mma16816(acc[mt][nt], afr[pa][mt], &bfr[nt >> 1][(nt & 1) * 2]);
                }
            }
        }
        __syncthreads();
    }

    // epilogue: C store + fused es/ed
    int head = bn * 2 + warp_n;
    const float* ws = a_src + head * 64;
    const float* wd = a_dst + head * 64;
    float wsv[16], wdv[16];
#pragma unroll
    for (int nt = 0; nt < 8; nt++) {
        int c0i = nt * 8 + (lane & 3) * 2;
        wsv[nt * 2] = ws[c0i]; wsv[nt * 2 + 1] = ws[c0i + 1];
        wdv[nt * 2] = wd[c0i]; wdv[nt * 2 + 1] = wd[c0i + 1];
    }
#pragma unroll
    for (int mt = 0; mt < 2; mt++) {
        int r0 = bm + warp_m * 32 + mt * 16 + (lane >> 2);
        int r1 = r0 + 8;
        float es0 = 0, ed0 = 0, es1 = 0, ed1 = 0;
#pragma unroll
        for (int nt = 0; nt < 8; nt++) {
            int c0i = bn * 128 + warp_n * 64 + nt * 8 + (lane & 3) * 2;
            es0 += acc[mt][nt][0] * wsv[nt * 2] + acc[mt][nt][1] * wsv[nt * 2 + 1];
            ed0 += acc[mt][nt][0] * wdv[nt * 2] + acc[mt][nt][1] * wdv[nt * 2 + 1];
            es1 += acc[mt][nt][2] * wsv[nt * 2] + acc[mt][nt][3] * wsv[nt * 2 + 1];
            ed1 += acc[mt][nt][2] * wdv[nt * 2] + acc[mt][nt][3] * wdv[nt * 2 + 1];
            *(float2*)(C + (size_t)r0 * 256 + c0i) = make_float2(acc[mt][nt][0], acc[mt][nt][1]);
            *(float2*)(C + (size_t)r1 * 256 + c0i) = make_float2(acc[mt][nt][2], acc[mt][nt][3]);
        }
#pragma unroll
        for (int d = 1; d < 4; d <<= 1) {
            es0 += __shfl_xor_sync(0xFFFFFFFFu, es0, d);
            ed0 += __shfl_xor_sync(0xFFFFFFFFu, ed0, d);
            es1 += __shfl_xor_sync(0xFFFFFFFFu, es1, d);
            ed1 += __shfl_xor_sync(0xFFFFFFFFu, ed1, d);
        }
        if ((lane & 3) == 0) {
            g_es[r0 * 4 + head] = es0; g_ed[r0 * 4 + head] = ed0;
            g_es[r1 * 4 + head] = es1; g_ed[r1 * 4 + head] = ed1;
        }
    }
}

// ---------------- GAT edge softmax + aggregation (warp-per-node, prefetch pipeline) ----------------
// EMIT_SPLIT: write fp16x2 splits (feeds layer-2 GEMM). SCORES: fused pooling logits.
// Edge processing order identical to CSR order (numerics unchanged vs R11).
template <bool EMIT_SPLIT, bool SCORES>
__global__ void __launch_bounds__(128) k_agg(const float* __restrict__ h,
                                             const float* __restrict__ bias,
                                             float* __restrict__ out,
                                             const float* __restrict__ p1_sw) {
    int n = (blockIdx.x * blockDim.x + threadIdx.x) >> 5;
    int lane = threadIdx.x & 31;
    if (n >= NN) return;
    int hd = lane >> 3;

    float myED = g_ed[n * 4 + hd];
    float esn = g_es[n * 4 + hd];
    int s0 = g_off[n], s1 = g_off[n + 1];

    float4 acc0, acc1;
    float den;
    {
        float w = __expf(lrelu02(esn + myED));
        den = w;
        const float4* hp = (const float4*)(h + (size_t)n * 256 + lane * 8);
        float4 v0 = hp[0], v1 = hp[1];
        acc0 = make_float4(w * v0.x, w * v0.y, w * v0.z, w * v0.w);
        acc1 = make_float4(w * v1.x, w * v1.y, w * v1.z, w * v1.w);
    }

    // software-pipelined edge loop: prefetch batch i+1's srcs+es during batch i
    int ssA[8];
    float eeA[8];
    {
        int cnt = s1 - s0;
#pragma unroll
        for (int u = 0; u < 8; u++) ssA[u] = (u < cnt && cnt > 0) ? __ldg(&g_srcs[s0 + u]) : n;
#pragma unroll
        for (int u = 0; u < 8; u++) eeA[u] = __ldg(&g_es[ssA[u] * 4 + hd]);
    }
    for (int base = s0; base < s1; base += 8) {
        int cnt = s1 - base;
        // prefetch next batch
        int ssB[8];
        int nb = base + 8;
        int cntB = s1 - nb;
#pragma unroll
        for (int u = 0; u < 8; u++) ssB[u] = (cntB > 0 && u < cntB) ? __ldg(&g_srcs[nb + u]) : n;
        // process current batch (order preserved)
#pragma unroll
        for (int u = 0; u < 8; u++) {
            float wu = (u < cnt) ? __expf(lrelu02(eeA[u] + myED)) : 0.f;
            den += wu;
            const float4* hp = (const float4*)(h + (size_t)ssA[u] * 256 + lane * 8);
            float4 v0 = hp[0], v1 = hp[1];
            acc0.x += wu * v0.x; acc0.y += wu * v0.y; acc0.z += wu * v0.z; acc0.w += wu * v0.w;
            acc1.x += wu * v1.x; acc1.y += wu * v1.y; acc1.z += wu * v1.z; acc1.w += wu * v1.w;
        }
        // es for next batch
#pragma unroll
        for (int u = 0; u < 8; u++) eeA[u] = __ldg(&g_es[ssB[u] * 4 + hd]);
#pragma unroll
        for (int u = 0; u < 8; u++) ssA[u] = ssB[u];
    }

    float inv = 1.f / (den + 1e-16f);
    const float* bp = bias + lane * 8;
    float o[8];
    o[0] = acc0.x * inv + bp[0]; o[1] = acc0.y * inv + bp[1];
    o[2] = acc0.z * inv + bp[2]; o[3] = acc0.w * inv + bp[3];
    o[4] = acc1.x * inv + bp[4]; o[5] = acc1.y * inv + bp[5];
    o[6] = acc1.z * inv + bp[6]; o[7] = acc1.w * inv + bp[7];
#pragma unroll
    for (int q = 0; q < 8; q++) o[q] = o[q] > 0.f ? o[q] : expm1f(o[q]);

    if (EMIT_SPLIT) {
        __half s0h[8], s1h[8];
#pragma unroll
        for (int q = 0; q < 8; q++) {
            float v = o[q];
            __half h0v = __float2half(v);
            float r = v - __half2float(h0v);
            s0h[q] = h0v; s1h[q] = __float2half(r);
        }
        size_t off = (size_t)n * 256 + lane * 8;
        *(uint4*)(g_a0 + off) = *(uint4*)s0h;
        *(uint4*)(g_a1 + off) = *(uint4*)s1h;
    } else {
        float* op = out + (size_t)n * 256 + lane * 8;
        *(float4*)op = make_float4(o[0], o[1], o[2], o[3]);
        *(float4*)(op + 4) = make_float4(o[4], o[5], o[6], o[7]);
    }

    if (SCORES) {
        float s1v = 0.f, s2v = 0.f;
#pragma unroll
        for (int q = 0; q < 8; q++) {
            s1v += o[q] * p1_sw[lane * 8 + q];
            s2v += o[q] * g_vvec[lane * 8 + q];
        }
#pragma unroll
        for (int d = 16; d > 0; d >>= 1) {
            s1v += __shfl_xor_sync(0xFFFFFFFFu, s1v, d);
            s2v += __shfl_xor_sync(0xFFFFFFFFu, s2v, d);
        }
        if (lane == 0) { g_l1[n] = s1v; g_l2[n] = s2v; }
    }
}

// ---------------- v = p1_tw @ p2_sw ----------------
__global__ void k_vvec(const float* __restrict__ p1_tw, const float* __restrict__ p2_sw) {
    int k = threadIdx.x;
    float s = 0.f;
    for (int c = 0; c < 256; c++) s += p1_tw[k * 256 + c] * p2_sw[c];
    g_vvec[k] = s;
}

// ---------------- per-graph: double top-k select + mean + classifier ----------------
__device__ __forceinline__ void bitonic_sort(unsigned long long* keys, int n, int tid, int nthreads) {
    for (int k = 2; k <= n; k <<= 1) {
        for (int j = k >> 1; j > 0; j >>= 1) {
            for (int t = tid; t < n; t += nthreads) {
                int ixj = t ^ j;
                if (ixj > t) {
                    bool up = ((t & k) == 0);
                    unsigned long long a = keys[t], b = keys[ixj];
                    if (up ? (a > b) : (a < b)) { keys[t] = b; keys[ixj] = a; }
                }
            }
            __syncthreads();
        }
    }
}

__global__ void __launch_bounds__(256) k_pool(
    const float* __restrict__ h2,
    const float* __restrict__ p1_tw, const float* __restrict__ p1_tb,
    const float* __restrict__ p2_tw, const float* __restrict__ p2_tb,
    const float* __restrict__ c1w, const float* __restrict__ c1b,
    const float* __restrict__ c2w, const float* __restrict__ c2b,
    float* __restrict__ out) {
    __shared__ unsigned long long keys[512];
    __shared__ int idx1[256];
    __shared__ int sel[128];
    __shared__ float bufA[256];
    __shared__ float bufB[256];
    __shared__ float zbuf[64];
    __shared__ float lg[2];

    int g = blockIdx.x;
    int tid = threadIdx.x;

    for (int t = tid; t < 512; t += 256) {
        float v = g_l1[g * NPGC + t];
        keys[t] = ((unsigned long long)(~fkey_asc(v)) << 32) | (unsigned int)t;
    }
    __syncthreads();
    bitonic_sort(keys, 512, tid, 256);
    idx1[tid] = (int)(keys[tid] & 0xFFFFFFFFu);
    __syncthreads();
    {
        float v = g_l2[g * NPGC + idx1[tid]];
        keys[tid] = ((unsigned long long)(~fkey_asc(v)) << 32) | (unsigned int)tid;
    }
    __syncthreads();
    bitonic_sort(keys, 256, tid, 256);
    if (tid < 128) sel[tid] = idx1[(int)(keys[tid] & 0xFFFFFFFFu)];
    __syncthreads();
    {
        float acc = 0.f;
        for (int j = 0; j < 128; j++) acc += h2[(size_t)(g * NPGC + sel[j]) * 256 + tid];
        bufA[tid] = acc * (1.f / 128.f);
    }
    __syncthreads();
    {
        float s = p1_tb[tid];
        for (int k = 0; k < 256; k++) s += bufA[k] * p1_tw[k * 256 + tid];
        bufB[tid] = s;
    }
    __syncthreads();
    {
        float s = p2_tb[tid];
        for (int k = 0; k < 256; k++) s += bufB[k] * p2_tw[k * 256 + tid];
        bufA[tid] = s;
    }
    __syncthreads();
    if (tid < 64) {
        float s = c1b[tid];
        for (int k = 0; k < 256; k++) s += bufA[k] * c1w[k * 64 + tid];
        zbuf[tid] = fmaxf(s, 0.f);
    }
    __syncthreads();
    if (tid < 2) {
        float s = c2b[tid];
        for (int k = 0; k < 64; k++) s += zbuf[k] * c2w[k * 2 + tid];
        lg[tid] = s;
    }
    __syncthreads();
    if (tid < 2) {
        float mx = fmaxf(lg[0], lg[1]);
        float lse = mx + logf(expf(lg[0] - mx) + expf(lg[1] - mx));
        out[g * 2 + tid] = lg[tid] - lse;
    }
}

// ---------------- launch ----------------
extern "C" void kernel_launch(void* const* d_in, const int* in_sizes, int n_in,
                              void* d_out, int out_size) {
    const float* x      = (const float*)d_in[0];
    const int*   ei     = (const int*)d_in[1];
    const float* W1     = (const float*)d_in[3];
    const float* a_src1 = (const float*)d_in[4];
    const float* a_dst1 = (const float*)d_in[5];
    const float* b1     = (const float*)d_in[6];
    const float* W2     = (const float*)d_in[7];
    const float* a_src2 = (const float*)d_in[8];
    const float* a_dst2 = (const float*)d_in[9];
    const float* b2     = (const float*)d_in[10];
    const float* p1_sw  = (const float*)d_in[11];
    const float* p1_tw  = (const float*)d_in[13];
    const float* p1_tb  = (const float*)d_in[14];
    const float* p2_sw  = (const float*)d_in[15];
    const float* p2_tw  = (const float*)d_in[17];
    const float* p2_tb  = (const float*)d_in[18];
    const float* c1w    = (const float*)d_in[19];
    const float* c1b    = (const float*)d_in[20];
    const float* c2w    = (const float*)d_in[21];
    const float* c2b    = (const float*)d_in[22];
    float* out = (float*)d_out;

    const int* src = ei;
    const int* dst = ei + EE;

    float* hlin; cudaGetSymbolAddress((void**)&hlin, g_buf0);
    float* h2;   cudaGetSymbolAddress((void**)&h2, g_h2);
    __half *a0, *a1, *b0, *b1s;
    cudaGetSymbolAddress((void**)&a0, g_a0);
    cudaGetSymbolAddress((void**)&a1, g_a1);
    cudaGetSymbolAddress((void**)&b0, g_b0);
    cudaGetSymbolAddress((void**)&b1s, g_b1);

    cudaFuncSetAttribute(k_mma3<4>, cudaFuncAttributeMaxDynamicSharedMemorySize, SMEM_MMA);
    cudaFuncSetAttribute(k_mma3<8>, cudaFuncAttributeMaxDynamicSharedMemorySize, SMEM_MMA);

    // fused CSR build (one block per graph)
    k_csr<<<BBG, 256>>>(src, dst);

    // layer 1: split x,W1 -> mma3 GEMM (fused es/ed) -> agg (emits fp16x2 splits)
    k_splitA<<<(NN * FINC) / 256, 256>>>(x, a0, a1, NN * FINC);
    k_splitW<<<(FINC * CCH) / 256, 256>>>(W1, b0, b1s, FINC);
    k_mma3<4><<<dim3(NN / 128, 2), 256, SMEM_MMA>>>(a0, a1, b0, b1s, hlin, a_src1, a_dst1);
    k_agg<true, false><<<NN / 4, 128>>>(hlin, b1, nullptr, nullptr);

    // layer 2 (vvec before agg: scores fused into agg epilogue)
    k_splitW<<<(CCH * CCH) / 256, 256>>>(W2, b0, b1s, CCH);
    k_vvec<<<1, 256>>>(p1_tw, p2_sw);
    k_mma3<8><<<dim3(NN / 128, 2), 256, SMEM_MMA>>>(a0, a1, b0, b1s, hlin, a_src2, a_dst2);
    k_agg<false, true><<<NN / 4, 128>>>(hlin, b2, h2, p1_sw);

    // final head
    k_pool<<<BBG, 256>>>(h2, p1_tw, p1_tb, p2_tw, p2_tb, c1w, c1b, c2w, c2b, out);
}